// round 11
// baseline (speedup 1.0000x reference)
#include <cuda_runtime.h>
#include <cuda_fp16.h>
#include <math.h>
#include <stdint.h>

#define B_ROWS 262144
#define HID 512
#define NB1 512
#define NPART 2048         // GEMM bm count = stats partials

// ---------------- device scratch ----------------
__device__ __half g_A[(size_t)B_ROWS * HID];      // t1 fp16 (256 MB)
__device__ __half g_B[HID * HID];                 // [n][k] = w2[k][n] fp16
__device__ __half g_h2h[(size_t)B_ROWS * HID];    // h2 fp16 (256 MB)
__device__ float  g_feat[B_ROWS * 4];
__device__ double g_p1[NB1 * 14];
__device__ float  g_W1eff[4 * HID];
__device__ float  g_shift1[HID];                  // folded: beta1 - meanX @ W1eff
__device__ float  g_p2s[(size_t)NPART * HID];
__device__ float  g_p2q[(size_t)NPART * HID];
__device__ float  g_a2[HID];
__device__ float  g_d2[HID];

// ---------------- PTX helpers (sm_80-level, safe at compute_103) ----------------
__device__ __forceinline__ uint32_t smem_u32(const void* p) {
    uint32_t a;
    asm("{ .reg .u64 t; cvta.to.shared.u64 t, %1; cvt.u32.u64 %0, t; }" : "=r"(a) : "l"(p));
    return a;
}
#define CP_ASYNC16(dst, src) \
    asm volatile("cp.async.cg.shared.global [%0], [%1], 16;" :: "r"(dst), "l"(src) : "memory")
#define CP_COMMIT() asm volatile("cp.async.commit_group;" ::: "memory")
#define CP_WAIT(n)  asm volatile("cp.async.wait_group %0;" :: "n"(n) : "memory")
#define LDSM_X4(r0, r1, r2, r3, addr) \
    asm volatile("ldmatrix.sync.aligned.m8n8.x4.shared.b16 {%0,%1,%2,%3}, [%4];" \
        : "=r"(r0), "=r"(r1), "=r"(r2), "=r"(r3) : "r"(addr))
#define MMA16816F16(d, a, b0, b1) \
    asm volatile("mma.sync.aligned.m16n8k16.row.col.f32.f16.f16.f32 " \
        "{%0,%1,%2,%3},{%4,%5,%6,%7},{%8,%9},{%0,%1,%2,%3};" \
        : "+f"((d)[0]), "+f"((d)[1]), "+f"((d)[2]), "+f"((d)[3]) \
        : "r"((a)[0]), "r"((a)[1]), "r"((a)[2]), "r"((a)[3]), "r"(b0), "r"(b1))

__device__ __forceinline__ float htanh(float x) {        // HW tanh (validated vs 1e-3 budget)
    float y;
    asm("tanh.approx.f32 %0, %1;" : "=f"(y) : "f"(x));
    return y;
}

// ---------------- K1: features + (sum, second-moment) partials ----------------
__global__ void __launch_bounds__(256) k1_feat(const float* __restrict__ x,
                                               const float* __restrict__ tset,
                                               const float* __restrict__ tenv,
                                               const float* __restrict__ ctab)
{
    __shared__ float sxs[9], sys[14], stab[9 * 14];
    __shared__ float srow[256][17];               // padded: conflict-free
    int tid = threadIdx.x;
    if (tid < 9)   sxs[tid] = tset[tid];
    if (tid < 14)  sys[tid] = tenv[tid];
    if (tid < 126) stab[tid] = ctab[tid];
    __syncthreads();

    double s0 = 0, s1 = 0, s2 = 0, s3 = 0;
    double m00 = 0, m01 = 0, m02 = 0, m03 = 0, m11 = 0, m12 = 0, m13 = 0,
           m22 = 0, m23 = 0, m33 = 0;

    for (int chunk = 0; chunk < 2; chunk++) {
        int base = blockIdx.x * 512 + chunk * 256;
        const float* gsrc = x + (size_t)base * 15;
        for (int i = tid; i < 256 * 15; i += 256) {
            srow[i / 15][i % 15] = gsrc[i];
        }
        __syncthreads();

        int r = base + tid;
        float amb = srow[tid][1], fl = srow[tid][2], fr = srow[tid][3];
        float incar = srow[tid][8], breq = srow[tid][9], cin = srow[tid][10];

        float yq = fminf(fmaxf(amb, sys[0]), sys[13]);
        int j = 0;
        #pragma unroll
        for (int k = 1; k <= 12; k++) j += (sys[k] <= yq);
        float y0 = sys[j], y1 = sys[j + 1];
        float ty = (yq - y0) / (y1 - y0);

        auto interp = [&](float xq) -> float {
            xq = fminf(fmaxf(xq, sxs[0]), sxs[8]);
            int i = 0;
            #pragma unroll
            for (int k = 1; k <= 7; k++) i += (sxs[k] <= xq);
            float x0 = sxs[i], x1 = sxs[i + 1];
            float tx = (xq - x0) / (x1 - x0);
            float f00 = stab[i * 14 + j],       f01 = stab[i * 14 + j + 1];
            float f10 = stab[(i + 1) * 14 + j], f11 = stab[(i + 1) * 14 + j + 1];
            return f00 * (1.f - tx) * (1.f - ty) + f10 * tx * (1.f - ty)
                 + f01 * (1.f - tx) * ty        + f11 * tx * ty;
        };

        float f0 = interp(fl) - incar;
        float f1 = interp(fr) - incar;
        float f2 = amb;
        float f3 = breq - cin;
        *(float4*)&g_feat[(size_t)r * 4] = make_float4(f0, f1, f2, f3);

        s0 += f0; s1 += f1; s2 += f2; s3 += f3;
        m00 += (double)f0 * f0; m01 += (double)f0 * f1; m02 += (double)f0 * f2; m03 += (double)f0 * f3;
        m11 += (double)f1 * f1; m12 += (double)f1 * f2; m13 += (double)f1 * f3;
        m22 += (double)f2 * f2; m23 += (double)f2 * f3; m33 += (double)f3 * f3;
        __syncthreads();
    }

    __shared__ double red[256];
    double vals[14] = {s0, s1, s2, s3, m00, m01, m02, m03, m11, m12, m13, m22, m23, m33};
    for (int q = 0; q < 14; q++) {
        red[tid] = vals[q];
        __syncthreads();
        for (int off = 128; off > 0; off >>= 1) {
            if (tid < off) red[tid] += red[tid + off];
            __syncthreads();
        }
        if (tid == 0) g_p1[blockIdx.x * 14 + q] = red[0];
        __syncthreads();
    }
}

// ---------------- K2: finalize layer-1 BN fold (mean folded into shift) ----------------
__global__ void k2_fin1(const float* __restrict__ w1,
                        const float* __restrict__ g1,
                        const float* __restrict__ beta1)
{
    __shared__ double acc[14];
    __shared__ float C[4][4];
    __shared__ float sMean[4];
    int tid = threadIdx.x;
    if (tid < 14) {
        double s = 0;
        for (int p = 0; p < NB1; p++) s += g_p1[p * 14 + tid];
        acc[tid] = s;
    }
    __syncthreads();
    if (tid == 0) {
        double inv = 1.0 / (double)B_ROWS;
        double mm[4];
        for (int a = 0; a < 4; a++) { mm[a] = acc[a] * inv; sMean[a] = (float)mm[a]; }
        double M[4][4];
        int idx = 4;
        for (int a = 0; a < 4; a++)
            for (int b = a; b < 4; b++) M[a][b] = acc[idx++] * inv;
        for (int a = 0; a < 4; a++)
            for (int b = a; b < 4; b++) {
                double c = M[a][b] - mm[a] * mm[b];
                C[a][b] = (float)c; C[b][a] = (float)c;
            }
    }
    __syncthreads();
    if (tid < HID) {
        float w[4];
        for (int a = 0; a < 4; a++) w[a] = w1[a * HID + tid];
        float var = 0.f;
        for (int a = 0; a < 4; a++)
            for (int b = 0; b < 4; b++) var += w[a] * C[a][b] * w[b];
        float s = g1[tid] * rsqrtf(var + 1e-5f);
        float we[4];
        for (int a = 0; a < 4; a++) { we[a] = w[a] * s; g_W1eff[a * HID + tid] = we[a]; }
        g_shift1[tid] = beta1[tid]
                      - (sMean[0] * we[0] + sMean[1] * we[1] + sMean[2] * we[2] + sMean[3] * we[3]);
    }
}

// ---------------- K2b: transpose w2 -> B [n][k] fp16 ----------------
__global__ void k2b_bsplit(const float* __restrict__ w2)
{
    int idx = blockIdx.x * 256 + threadIdx.x;
    int n = idx >> 9, k = idx & 511;
    g_B[n * HID + k] = __float2half_rn(w2[k * HID + n]);
}

// ---------------- K3a: t1 = tanh(feat @ W1eff + shift) -> fp16, 16B stores ----------------
// 8 cols x 8 rows per thread; 64 threads share a row-group (broadcast feat loads).
__global__ void __launch_bounds__(256) k3a_layer1()
{
    int tid = threadIdx.x;
    int jc = (tid & 63) * 8;
    int r0 = blockIdx.x * 32 + (tid >> 6) * 8;

    float w[4][8], sh[8];
    #pragma unroll
    for (int u = 0; u < 8; u++) {
        #pragma unroll
        for (int a = 0; a < 4; a++) w[a][u] = g_W1eff[a * HID + jc + u];
        sh[u] = g_shift1[jc + u];
    }

    #pragma unroll
    for (int rr = 0; rr < 8; rr++) {
        int r = r0 + rr;
        float4 f = *(const float4*)&g_feat[(size_t)r * 4];
        uint32_t hp[4];
        #pragma unroll
        for (int u = 0; u < 8; u += 2) {
            float v0 = f.x * w[0][u]     + f.y * w[1][u]     + f.z * w[2][u]     + f.w * w[3][u]     + sh[u];
            float v1 = f.x * w[0][u + 1] + f.y * w[1][u + 1] + f.z * w[2][u + 1] + f.w * w[3][u + 1] + sh[u + 1];
            __half2 p = __floats2half2_rn(htanh(v0), htanh(v1));
            hp[u >> 1] = *(uint32_t*)&p;
        }
        *(uint4*)(g_A + (size_t)r * HID + jc) = make_uint4(hp[0], hp[1], hp[2], hp[3]);
    }
}

// ---------------- K3b: h2 = t1 @ w2 (fp16 mma.sync) + fused column stats ----------------
// CTA tile 128x128, 4 warps (warp tile 64x64), KSTAGE=64, 3-deep cp.async ring,
// intra-stage register fragment double-buffering.
#define KSTAGE 64
#define ROWPAD 144                     // 128B data + 16B pad (conflict-free ldmatrix)
#define OFF_A 0
#define OFF_B (128 * ROWPAD)           // 18432
#define STAGEB (256 * ROWPAD)          // 36864
#define NSTG 3
#define GEMM_SMEM (NSTG * STAGEB)      // 110592 (2 CTAs/SM = 221 KB)
#define RSTRIDE 136                    // epilogue staging row stride in halves (272B)
#define SST_OFF 36864                  // stats scratch (buffer-1 region, post-loop only)
#define GTHREADS 128

__global__ void __launch_bounds__(GTHREADS, 2) k3b_gemm()
{
    extern __shared__ char smem[];
    const uint32_t sb = smem_u32(smem);
    const int tid = threadIdx.x;
    const int wid = tid >> 5, lane = tid & 31;
    const int bn = blockIdx.x, bm = blockIdx.y;
    const size_t arow0 = (size_t)bm * 128;
    const int ncol0 = bn * 128;

    auto issue_stage = [&](int st) {
        uint32_t stg = sb + (st % NSTG) * STAGEB;
        int kk = st * KSTAGE;
        #pragma unroll
        for (int h = 0; h < 16; h++) {
            int idx = tid + h * GTHREADS;       // 2048 chunks of 16B
            int r = (idx & 1023) >> 3, c = idx & 7;
            uint32_t doff = (uint32_t)r * ROWPAD + c * 16;
            if (idx < 1024) {
                CP_ASYNC16(stg + OFF_A + doff, g_A + (arow0 + r) * HID + kk + c * 8);
            } else {
                CP_ASYNC16(stg + OFF_B + doff, g_B + (size_t)(ncol0 + r) * HID + kk + c * 8);
            }
        }
    };

    issue_stage(0); CP_COMMIT();
    issue_stage(1); CP_COMMIT();

    const int warp_m = wid & 1;        // 2 warp rows of 64
    const int warp_n = wid >> 1;       // 2 warp cols of 64

    float acc[4][8][4];
    #pragma unroll
    for (int i = 0; i < 4; i++)
        #pragma unroll
        for (int j = 0; j < 8; j++)
            #pragma unroll
            for (int q = 0; q < 4; q++) acc[i][j][q] = 0.f;

    const int a_row = warp_m * 64 + (lane & 15);
    const uint32_t a_koff = (lane >> 4) * 16;
    const int b_row = warp_n * 64 + (lane & 7) + ((lane >> 4) & 1) * 8;
    const uint32_t b_koff = ((lane >> 3) & 1) * 16;

    // register fragment double buffers
    uint32_t fa[2][4][4], fb[2][4][4];

#define LOADF(STG, KS, BUF) do {                                                  \
        uint32_t _kb = (uint32_t)(KS) * 32;                                       \
        _Pragma("unroll")                                                         \
        for (int _im = 0; _im < 4; _im++) {                                       \
            uint32_t _aa = (STG) + OFF_A + (uint32_t)(a_row + _im * 16) * ROWPAD + _kb + a_koff; \
            LDSM_X4(fa[BUF][_im][0], fa[BUF][_im][1], fa[BUF][_im][2], fa[BUF][_im][3], _aa);    \
        }                                                                         \
        _Pragma("unroll")                                                         \
        for (int _ng = 0; _ng < 4; _ng++) {                                       \
            uint32_t _bb = (STG) + OFF_B + (uint32_t)(b_row + _ng * 16) * ROWPAD + _kb + b_koff; \
            LDSM_X4(fb[BUF][_ng][0], fb[BUF][_ng][1], fb[BUF][_ng][2], fb[BUF][_ng][3], _bb);    \
        }                                                                         \
    } while (0)

#define MMA_ALL(BUF) do {                                                         \
        _Pragma("unroll")                                                         \
        for (int _ng = 0; _ng < 4; _ng++) {                                       \
            _Pragma("unroll")                                                     \
            for (int _im = 0; _im < 4; _im++) {                                   \
                MMA16816F16(acc[_im][_ng * 2 + 0], fa[BUF][_im], fb[BUF][_ng][0], fb[BUF][_ng][1]); \
                MMA16816F16(acc[_im][_ng * 2 + 1], fa[BUF][_im], fb[BUF][_ng][2], fb[BUF][_ng][3]); \
            }                                                                     \
        }                                                                         \
    } while (0)

    for (int s = 0; s < 8; s++) {
        CP_WAIT(1);
        __syncthreads();

        uint32_t stg = sb + (s % NSTG) * STAGEB;
        LOADF(stg, 0, 0);               // only exposed LDSM latency per stage

        #pragma unroll
        for (int ks = 0; ks < 4; ks++) {
            const int cb = ks & 1;
            if (ks < 3) LOADF(stg, ks + 1, cb ^ 1);   // prefetch next k-step
            if (ks == 0) {
                if (s + 2 < 8) issue_stage(s + 2);
                CP_COMMIT();
            }
            MMA_ALL(cb);
        }
    }
    CP_WAIT(0);
    __syncthreads();

    // ---- epilogue 1: pack fp16 into smem staging (conflict-free) ----
    __half* hst = (__half*)smem;
    #pragma unroll
    for (int im = 0; im < 4; im++) {
        #pragma unroll
        for (int half = 0; half < 2; half++) {
            int row = warp_m * 64 + im * 16 + (lane >> 2) + half * 8;
            int colb = warp_n * 64 + (lane & 3) * 2;
            #pragma unroll
            for (int ng2 = 0; ng2 < 8; ng2++) {
                __half2 hv = __floats2half2_rn(acc[im][ng2][2 * half], acc[im][ng2][2 * half + 1]);
                *(__half2*)&hst[row * RSTRIDE + colb + ng2 * 8] = hv;
            }
        }
    }

    // ---- epilogue 2: fused column sum/sumsq partials ----
    float* sst = (float*)(smem + SST_OFF);
    #pragma unroll
    for (int ng2 = 0; ng2 < 8; ng2++) {
        #pragma unroll
        for (int e = 0; e < 2; e++) {
            float s = 0.f, q = 0.f;
            #pragma unroll
            for (int im = 0; im < 4; im++) {
                #pragma unroll
                for (int half = 0; half < 2; half++) {
                    float v = acc[im][ng2][2 * half + e];
                    s += v; q += v * v;
                }
            }
            #pragma unroll
            for (int off = 4; off < 32; off <<= 1) {
                s += __shfl_xor_sync(0xffffffffu, s, off);
                q += __shfl_xor_sync(0xffffffffu, q, off);
            }
            if (lane < 4) {
                int col = warp_n * 64 + ng2 * 8 + lane * 2 + e;
                sst[(warp_m * 128 + col) * 2 + 0] = s;
                sst[(warp_m * 128 + col) * 2 + 1] = q;
            }
        }
    }
    __syncthreads();

    // ---- epilogue 3: coalesced fp16 stores from staging ----
    #pragma unroll
    for (int it = 0; it < 16; it++) {
        int g = it * GTHREADS + tid;
        int row = g >> 4, ch = g & 15;
        uint4 v = *(uint4*)&hst[row * RSTRIDE + ch * 8];
        *(uint4*)(g_h2h + (arow0 + row) * HID + ncol0 + ch * 8) = v;
    }

    // ---- epilogue 4: reduce stats across warp_m, write partials ----
    #pragma unroll
    for (int g = tid; g < 256; g += GTHREADS) {
        int col = g >> 1, sq = g & 1;
        float v = sst[(0 * 128 + col) * 2 + sq] + sst[(1 * 128 + col) * 2 + sq];
        size_t gidx = (size_t)bm * HID + bn * 128 + col;
        if (sq == 0) g_p2s[gidx] = v; else g_p2q[gidx] = v;
    }
#undef LOADF
#undef MMA_ALL
}

// ---------------- K5: finalize layer-2 BN fold (one block per column) ----------------
__global__ void k5_fin2(const float* __restrict__ g2, const float* __restrict__ beta2)
{
    int c = blockIdx.x;
    int t = threadIdx.x;
    double s = 0, q = 0;
    for (int p = t; p < NPART; p += 256) {
        s += (double)g_p2s[(size_t)p * HID + c];
        q += (double)g_p2q[(size_t)p * HID + c];
    }
    __shared__ double rs[256], rq[256];
    rs[t] = s; rq[t] = q;
    __syncthreads();
    for (int off = 128; off > 0; off >>= 1) {
        if (t < off) { rs[t] += rs[t + off]; rq[t] += rq[t + off]; }
        __syncthreads();
    }
    if (t == 0) {
        double mu  = rs[0] / (double)B_ROWS;
        double var = rq[0] / (double)B_ROWS - mu * mu;
        float a = g2[c] * rsqrtf((float)var + 1e-5f);
        g_a2[c] = a;
        g_d2[c] = beta2[c] - (float)mu * a;
    }
}

// ---------------- K6: out = tanh(a2*h2 + d2) @ w3 + b3 (HW tanh, reg consts) ----------------
__global__ void __launch_bounds__(256) k6_out(const float* __restrict__ w3,
                                              const float* __restrict__ b3,
                                              float* __restrict__ out)
{
    int t = threadIdx.x;
    int warp = t >> 5, lane = t & 31;
    float bias = b3[0];

    float ra[16], rd[16], rw[16];
    #pragma unroll
    for (int p = 0; p < 2; p++) {
        int c0 = p * 256 + lane * 8;
        #pragma unroll
        for (int u = 0; u < 8; u++) {
            ra[p * 8 + u] = g_a2[c0 + u];
            rd[p * 8 + u] = g_d2[c0 + u];
            rw[p * 8 + u] = w3[c0 + u];
        }
    }

    int gw = blockIdx.x * 8 + warp;
    int stride = gridDim.x * 8;
    for (int r = gw; r < B_ROWS; r += stride) {
        const __half* row = g_h2h + (size_t)r * HID;
        float acc = 0.f;
        #pragma unroll
        for (int p = 0; p < 2; p++) {
            int c0 = p * 256 + lane * 8;
            uint4 v = *(const uint4*)(row + c0);
            float2 f0 = __half22float2(*(__half2*)&v.x);
            float2 f1 = __half22float2(*(__half2*)&v.y);
            float2 f2 = __half22float2(*(__half2*)&v.z);
            float2 f3 = __half22float2(*(__half2*)&v.w);
            float hv[8] = {f0.x, f0.y, f1.x, f1.y, f2.x, f2.y, f3.x, f3.y};
            #pragma unroll
            for (int u = 0; u < 8; u++) {
                int q = p * 8 + u;
                acc += htanh(fmaf(ra[q], hv[u], rd[q])) * rw[q];
            }
        }
        #pragma unroll
        for (int off = 16; off; off >>= 1) acc += __shfl_xor_sync(0xffffffffu, acc, off);
        if (lane == 0) out[r] = acc + bias;
    }
}

// ---------------- launch ----------------
extern "C" void kernel_launch(void* const* d_in, const int* in_sizes, int n_in,
                              void* d_out, int out_size)
{
    const float* x     = (const float*)d_in[0];
    const float* tset  = (const float*)d_in[1];
    const float* tenv  = (const float*)d_in[2];
    const float* ctab  = (const float*)d_in[3];
    const float* w1    = (const float*)d_in[4];
    const float* g1    = (const float*)d_in[6];
    const float* beta1 = (const float*)d_in[7];
    const float* w2    = (const float*)d_in[8];
    const float* g2    = (const float*)d_in[10];
    const float* beta2 = (const float*)d_in[11];
    const float* w3    = (const float*)d_in[12];
    const float* b3    = (const float*)d_in[13];
    float* out = (float*)d_out;

    static bool attr_set = false;
    if (!attr_set) {
        cudaFuncSetAttribute(k3b_gemm, cudaFuncAttributeMaxDynamicSharedMemorySize, GEMM_SMEM);
        attr_set = true;
    }

    k1_feat<<<NB1, 256>>>(x, tset, tenv, ctab);
    k2_fin1<<<1, 512>>>(w1, g1, beta1);
    k2b_bsplit<<<HID * HID / 256, 256>>>(w2);
    k3a_layer1<<<B_ROWS / 32, 256>>>();
    dim3 g3(4, B_ROWS / 128);
    k3b_gemm<<<g3, GTHREADS, GEMM_SMEM>>>();
    k5_fin2<<<HID, 256>>>(g2, beta2);
    k6_out<<<4096, 256>>>(w3, b3, out);
}

// round 12
// speedup vs baseline: 1.0684x; 1.0684x over previous
#include <cuda_runtime.h>
#include <cuda_fp16.h>
#include <math.h>
#include <stdint.h>

#define B_ROWS 262144
#define HID 512
#define NB1 512
#define NPART 2048         // GEMM bm count = stats partials

// ---------------- device scratch ----------------
__device__ __half g_A[(size_t)B_ROWS * HID];      // t1 fp16 (256 MB)
__device__ __half g_B[HID * HID];                 // [n][k] = w2[k][n] fp16
__device__ __half g_h2h[(size_t)B_ROWS * HID];    // h2 fp16 (256 MB)
__device__ float  g_feat[B_ROWS * 4];
__device__ double g_p1[NB1 * 14];
__device__ float  g_W1eff[4 * HID];
__device__ float  g_shift1[HID];                  // folded: beta1 - meanX @ W1eff
__device__ float  g_p2s[(size_t)NPART * HID];
__device__ float  g_p2q[(size_t)NPART * HID];
__device__ float  g_a2[HID];
__device__ float  g_d2[HID];

// ---------------- PTX helpers (sm_80-level, safe at compute_103) ----------------
__device__ __forceinline__ uint32_t smem_u32(const void* p) {
    uint32_t a;
    asm("{ .reg .u64 t; cvta.to.shared.u64 t, %1; cvt.u32.u64 %0, t; }" : "=r"(a) : "l"(p));
    return a;
}
#define CP_ASYNC16(dst, src) \
    asm volatile("cp.async.cg.shared.global [%0], [%1], 16;" :: "r"(dst), "l"(src) : "memory")
#define CP_COMMIT() asm volatile("cp.async.commit_group;" ::: "memory")
#define CP_WAIT(n)  asm volatile("cp.async.wait_group %0;" :: "n"(n) : "memory")
#define LDSM_X4(r0, r1, r2, r3, addr) \
    asm volatile("ldmatrix.sync.aligned.m8n8.x4.shared.b16 {%0,%1,%2,%3}, [%4];" \
        : "=r"(r0), "=r"(r1), "=r"(r2), "=r"(r3) : "r"(addr))
#define MMA16816F16(d, a, b0, b1) \
    asm volatile("mma.sync.aligned.m16n8k16.row.col.f32.f16.f16.f32 " \
        "{%0,%1,%2,%3},{%4,%5,%6,%7},{%8,%9},{%0,%1,%2,%3};" \
        : "+f"((d)[0]), "+f"((d)[1]), "+f"((d)[2]), "+f"((d)[3]) \
        : "r"((a)[0]), "r"((a)[1]), "r"((a)[2]), "r"((a)[3]), "r"(b0), "r"(b1))

__device__ __forceinline__ float htanh(float x) {        // HW tanh (validated vs 1e-3 budget)
    float y;
    asm("tanh.approx.f32 %0, %1;" : "=f"(y) : "f"(x));
    return y;
}

// ---------------- K1: features + (sum, second-moment) partials ----------------
__global__ void __launch_bounds__(256) k1_feat(const float* __restrict__ x,
                                               const float* __restrict__ tset,
                                               const float* __restrict__ tenv,
                                               const float* __restrict__ ctab)
{
    __shared__ float sxs[9], sys[14], stab[9 * 14];
    __shared__ float srow[256][17];               // padded: conflict-free
    int tid = threadIdx.x;
    if (tid < 9)   sxs[tid] = tset[tid];
    if (tid < 14)  sys[tid] = tenv[tid];
    if (tid < 126) stab[tid] = ctab[tid];
    __syncthreads();

    double s0 = 0, s1 = 0, s2 = 0, s3 = 0;
    double m00 = 0, m01 = 0, m02 = 0, m03 = 0, m11 = 0, m12 = 0, m13 = 0,
           m22 = 0, m23 = 0, m33 = 0;

    for (int chunk = 0; chunk < 2; chunk++) {
        int base = blockIdx.x * 512 + chunk * 256;
        const float* gsrc = x + (size_t)base * 15;
        for (int i = tid; i < 256 * 15; i += 256) {
            srow[i / 15][i % 15] = gsrc[i];
        }
        __syncthreads();

        int r = base + tid;
        float amb = srow[tid][1], fl = srow[tid][2], fr = srow[tid][3];
        float incar = srow[tid][8], breq = srow[tid][9], cin = srow[tid][10];

        float yq = fminf(fmaxf(amb, sys[0]), sys[13]);
        int j = 0;
        #pragma unroll
        for (int k = 1; k <= 12; k++) j += (sys[k] <= yq);
        float y0 = sys[j], y1 = sys[j + 1];
        float ty = (yq - y0) / (y1 - y0);

        auto interp = [&](float xq) -> float {
            xq = fminf(fmaxf(xq, sxs[0]), sxs[8]);
            int i = 0;
            #pragma unroll
            for (int k = 1; k <= 7; k++) i += (sxs[k] <= xq);
            float x0 = sxs[i], x1 = sxs[i + 1];
            float tx = (xq - x0) / (x1 - x0);
            float f00 = stab[i * 14 + j],       f01 = stab[i * 14 + j + 1];
            float f10 = stab[(i + 1) * 14 + j], f11 = stab[(i + 1) * 14 + j + 1];
            return f00 * (1.f - tx) * (1.f - ty) + f10 * tx * (1.f - ty)
                 + f01 * (1.f - tx) * ty        + f11 * tx * ty;
        };

        float f0 = interp(fl) - incar;
        float f1 = interp(fr) - incar;
        float f2 = amb;
        float f3 = breq - cin;
        *(float4*)&g_feat[(size_t)r * 4] = make_float4(f0, f1, f2, f3);

        s0 += f0; s1 += f1; s2 += f2; s3 += f3;
        m00 += (double)f0 * f0; m01 += (double)f0 * f1; m02 += (double)f0 * f2; m03 += (double)f0 * f3;
        m11 += (double)f1 * f1; m12 += (double)f1 * f2; m13 += (double)f1 * f3;
        m22 += (double)f2 * f2; m23 += (double)f2 * f3; m33 += (double)f3 * f3;
        __syncthreads();
    }

    __shared__ double red[256];
    double vals[14] = {s0, s1, s2, s3, m00, m01, m02, m03, m11, m12, m13, m22, m23, m33};
    for (int q = 0; q < 14; q++) {
        red[tid] = vals[q];
        __syncthreads();
        for (int off = 128; off > 0; off >>= 1) {
            if (tid < off) red[tid] += red[tid + off];
            __syncthreads();
        }
        if (tid == 0) g_p1[blockIdx.x * 14 + q] = red[0];
        __syncthreads();
    }
}

// ---------------- K2: finalize layer-1 BN fold (mean folded into shift) ----------------
__global__ void k2_fin1(const float* __restrict__ w1,
                        const float* __restrict__ g1,
                        const float* __restrict__ beta1)
{
    __shared__ double acc[14];
    __shared__ float C[4][4];
    __shared__ float sMean[4];
    int tid = threadIdx.x;
    if (tid < 14) {
        double s = 0;
        for (int p = 0; p < NB1; p++) s += g_p1[p * 14 + tid];
        acc[tid] = s;
    }
    __syncthreads();
    if (tid == 0) {
        double inv = 1.0 / (double)B_ROWS;
        double mm[4];
        for (int a = 0; a < 4; a++) { mm[a] = acc[a] * inv; sMean[a] = (float)mm[a]; }
        double M[4][4];
        int idx = 4;
        for (int a = 0; a < 4; a++)
            for (int b = a; b < 4; b++) M[a][b] = acc[idx++] * inv;
        for (int a = 0; a < 4; a++)
            for (int b = a; b < 4; b++) {
                double c = M[a][b] - mm[a] * mm[b];
                C[a][b] = (float)c; C[b][a] = (float)c;
            }
    }
    __syncthreads();
    if (tid < HID) {
        float w[4];
        for (int a = 0; a < 4; a++) w[a] = w1[a * HID + tid];
        float var = 0.f;
        for (int a = 0; a < 4; a++)
            for (int b = 0; b < 4; b++) var += w[a] * C[a][b] * w[b];
        float s = g1[tid] * rsqrtf(var + 1e-5f);
        float we[4];
        for (int a = 0; a < 4; a++) { we[a] = w[a] * s; g_W1eff[a * HID + tid] = we[a]; }
        g_shift1[tid] = beta1[tid]
                      - (sMean[0] * we[0] + sMean[1] * we[1] + sMean[2] * we[2] + sMean[3] * we[3]);
    }
}

// ---------------- K2b: transpose w2 -> B [n][k] fp16 ----------------
__global__ void k2b_bsplit(const float* __restrict__ w2)
{
    int idx = blockIdx.x * 256 + threadIdx.x;
    int n = idx >> 9, k = idx & 511;
    g_B[n * HID + k] = __float2half_rn(w2[k * HID + n]);
}

// ---------------- K3a: t1 = tanh(feat @ W1eff + shift) -> fp16 (R10 version) ----------------
__global__ void __launch_bounds__(256) k3a_layer1()
{
    int tid = threadIdx.x;
    int jc = (tid & 127) * 4;
    int r0 = blockIdx.x * 16 + (tid >> 7) * 8;

    float4 w0 = *(const float4*)&g_W1eff[0 * HID + jc];
    float4 w1v = *(const float4*)&g_W1eff[1 * HID + jc];
    float4 w2v = *(const float4*)&g_W1eff[2 * HID + jc];
    float4 w3v = *(const float4*)&g_W1eff[3 * HID + jc];
    float4 sh = *(const float4*)&g_shift1[jc];

    #pragma unroll
    for (int rr = 0; rr < 8; rr++) {
        int r = r0 + rr;
        float4 f = *(const float4*)&g_feat[(size_t)r * 4];
        float v0 = f.x * w0.x + f.y * w1v.x + f.z * w2v.x + f.w * w3v.x + sh.x;
        float v1 = f.x * w0.y + f.y * w1v.y + f.z * w2v.y + f.w * w3v.y + sh.y;
        float v2 = f.x * w0.z + f.y * w1v.z + f.z * w2v.z + f.w * w3v.z + sh.z;
        float v3 = f.x * w0.w + f.y * w1v.w + f.z * w2v.w + f.w * w3v.w + sh.w;
        __half2 p0 = __floats2half2_rn(htanh(v0), htanh(v1));
        __half2 p1 = __floats2half2_rn(htanh(v2), htanh(v3));
        uint2 pk = make_uint2(*(uint32_t*)&p0, *(uint32_t*)&p1);
        *(uint2*)(g_A + (size_t)r * HID + jc) = pk;
    }
}

// ---------------- K3b: h2 = t1 @ w2 (fp16 mma.sync) + fused column stats ----------------
// CTA tile 128x128, 4 warps (warp tile 64x64), KSTAGE=64, 3-deep cp.async ring,
// intra-stage register fragment double-buffering. (R11 GEMM, kept.)
#define KSTAGE 64
#define ROWPAD 144                     // 128B data + 16B pad (conflict-free ldmatrix)
#define OFF_A 0
#define OFF_B (128 * ROWPAD)           // 18432
#define STAGEB (256 * ROWPAD)          // 36864
#define NSTG 3
#define GEMM_SMEM (NSTG * STAGEB)      // 110592 (2 CTAs/SM = 221 KB)
#define RSTRIDE 136                    // epilogue staging row stride in halves (272B)
#define SST_OFF 36864                  // stats scratch (buffer-1 region, post-loop only)
#define GTHREADS 128

__global__ void __launch_bounds__(GTHREADS, 2) k3b_gemm()
{
    extern __shared__ char smem[];
    const uint32_t sb = smem_u32(smem);
    const int tid = threadIdx.x;
    const int wid = tid >> 5, lane = tid & 31;
    const int bn = blockIdx.x, bm = blockIdx.y;
    const size_t arow0 = (size_t)bm * 128;
    const int ncol0 = bn * 128;

    auto issue_stage = [&](int st) {
        uint32_t stg = sb + (st % NSTG) * STAGEB;
        int kk = st * KSTAGE;
        #pragma unroll
        for (int h = 0; h < 16; h++) {
            int idx = tid + h * GTHREADS;       // 2048 chunks of 16B
            int r = (idx & 1023) >> 3, c = idx & 7;
            uint32_t doff = (uint32_t)r * ROWPAD + c * 16;
            if (idx < 1024) {
                CP_ASYNC16(stg + OFF_A + doff, g_A + (arow0 + r) * HID + kk + c * 8);
            } else {
                CP_ASYNC16(stg + OFF_B + doff, g_B + (size_t)(ncol0 + r) * HID + kk + c * 8);
            }
        }
    };

    issue_stage(0); CP_COMMIT();
    issue_stage(1); CP_COMMIT();

    const int warp_m = wid & 1;        // 2 warp rows of 64
    const int warp_n = wid >> 1;       // 2 warp cols of 64

    float acc[4][8][4];
    #pragma unroll
    for (int i = 0; i < 4; i++)
        #pragma unroll
        for (int j = 0; j < 8; j++)
            #pragma unroll
            for (int q = 0; q < 4; q++) acc[i][j][q] = 0.f;

    const int a_row = warp_m * 64 + (lane & 15);
    const uint32_t a_koff = (lane >> 4) * 16;
    const int b_row = warp_n * 64 + (lane & 7) + ((lane >> 4) & 1) * 8;
    const uint32_t b_koff = ((lane >> 3) & 1) * 16;

    // register fragment double buffers
    uint32_t fa[2][4][4], fb[2][4][4];

#define LOADF(STG, KS, BUF) do {                                                  \
        uint32_t _kb = (uint32_t)(KS) * 32;                                       \
        _Pragma("unroll")                                                         \
        for (int _im = 0; _im < 4; _im++) {                                       \
            uint32_t _aa = (STG) + OFF_A + (uint32_t)(a_row + _im * 16) * ROWPAD + _kb + a_koff; \
            LDSM_X4(fa[BUF][_im][0], fa[BUF][_im][1], fa[BUF][_im][2], fa[BUF][_im][3], _aa);    \
        }                                                                         \
        _Pragma("unroll")                                                         \
        for (int _ng = 0; _ng < 4; _ng++) {                                       \
            uint32_t _bb = (STG) + OFF_B + (uint32_t)(b_row + _ng * 16) * ROWPAD + _kb + b_koff; \
            LDSM_X4(fb[BUF][_ng][0], fb[BUF][_ng][1], fb[BUF][_ng][2], fb[BUF][_ng][3], _bb);    \
        }                                                                         \
    } while (0)

#define MMA_ALL(BUF) do {                                                         \
        _Pragma("unroll")                                                         \
        for (int _ng = 0; _ng < 4; _ng++) {                                       \
            _Pragma("unroll")                                                     \
            for (int _im = 0; _im < 4; _im++) {                                   \
                MMA16816F16(acc[_im][_ng * 2 + 0], fa[BUF][_im], fb[BUF][_ng][0], fb[BUF][_ng][1]); \
                MMA16816F16(acc[_im][_ng * 2 + 1], fa[BUF][_im], fb[BUF][_ng][2], fb[BUF][_ng][3]); \
            }                                                                     \
        }                                                                         \
    } while (0)

    for (int s = 0; s < 8; s++) {
        CP_WAIT(1);
        __syncthreads();

        uint32_t stg = sb + (s % NSTG) * STAGEB;
        LOADF(stg, 0, 0);               // only exposed LDSM latency per stage

        #pragma unroll
        for (int ks = 0; ks < 4; ks++) {
            const int cb = ks & 1;
            if (ks < 3) LOADF(stg, ks + 1, cb ^ 1);   // prefetch next k-step
            if (ks == 0) {
                if (s + 2 < 8) issue_stage(s + 2);
                CP_COMMIT();
            }
            MMA_ALL(cb);
        }
    }
    CP_WAIT(0);
    __syncthreads();

    // ---- epilogue 1: pack fp16 into smem staging (conflict-free) ----
    __half* hst = (__half*)smem;
    #pragma unroll
    for (int im = 0; im < 4; im++) {
        #pragma unroll
        for (int half = 0; half < 2; half++) {
            int row = warp_m * 64 + im * 16 + (lane >> 2) + half * 8;
            int colb = warp_n * 64 + (lane & 3) * 2;
            #pragma unroll
            for (int ng2 = 0; ng2 < 8; ng2++) {
                __half2 hv = __floats2half2_rn(acc[im][ng2][2 * half], acc[im][ng2][2 * half + 1]);
                *(__half2*)&hst[row * RSTRIDE + colb + ng2 * 8] = hv;
            }
        }
    }

    // ---- epilogue 2: fused column sum/sumsq partials ----
    float* sst = (float*)(smem + SST_OFF);
    #pragma unroll
    for (int ng2 = 0; ng2 < 8; ng2++) {
        #pragma unroll
        for (int e = 0; e < 2; e++) {
            float s = 0.f, q = 0.f;
            #pragma unroll
            for (int im = 0; im < 4; im++) {
                #pragma unroll
                for (int half = 0; half < 2; half++) {
                    float v = acc[im][ng2][2 * half + e];
                    s += v; q += v * v;
                }
            }
            #pragma unroll
            for (int off = 4; off < 32; off <<= 1) {
                s += __shfl_xor_sync(0xffffffffu, s, off);
                q += __shfl_xor_sync(0xffffffffu, q, off);
            }
            if (lane < 4) {
                int col = warp_n * 64 + ng2 * 8 + lane * 2 + e;
                sst[(warp_m * 128 + col) * 2 + 0] = s;
                sst[(warp_m * 128 + col) * 2 + 1] = q;
            }
        }
    }
    __syncthreads();

    // ---- epilogue 3: coalesced fp16 stores from staging ----
    #pragma unroll
    for (int it = 0; it < 16; it++) {
        int g = it * GTHREADS + tid;
        int row = g >> 4, ch = g & 15;
        uint4 v = *(uint4*)&hst[row * RSTRIDE + ch * 8];
        *(uint4*)(g_h2h + (arow0 + row) * HID + ncol0 + ch * 8) = v;
    }

    // ---- epilogue 4: reduce stats across warp_m, write partials ----
    #pragma unroll
    for (int g = tid; g < 256; g += GTHREADS) {
        int col = g >> 1, sq = g & 1;
        float v = sst[(0 * 128 + col) * 2 + sq] + sst[(1 * 128 + col) * 2 + sq];
        size_t gidx = (size_t)bm * HID + bn * 128 + col;
        if (sq == 0) g_p2s[gidx] = v; else g_p2q[gidx] = v;
    }
#undef LOADF
#undef MMA_ALL
}

// ---------------- K5: finalize layer-2 BN fold (one block per column) ----------------
__global__ void k5_fin2(const float* __restrict__ g2, const float* __restrict__ beta2)
{
    int c = blockIdx.x;
    int t = threadIdx.x;
    double s = 0, q = 0;
    for (int p = t; p < NPART; p += 256) {
        s += (double)g_p2s[(size_t)p * HID + c];
        q += (double)g_p2q[(size_t)p * HID + c];
    }
    __shared__ double rs[256], rq[256];
    rs[t] = s; rq[t] = q;
    __syncthreads();
    for (int off = 128; off > 0; off >>= 1) {
        if (t < off) { rs[t] += rs[t + off]; rq[t] += rq[t + off]; }
        __syncthreads();
    }
    if (t == 0) {
        double mu  = rs[0] / (double)B_ROWS;
        double var = rq[0] / (double)B_ROWS - mu * mu;
        float a = g2[c] * rsqrtf((float)var + 1e-5f);
        g_a2[c] = a;
        g_d2[c] = beta2[c] - (float)mu * a;
    }
}

// ---------------- K6: out = tanh(a2*h2 + d2) @ w3 + b3 (HW tanh, reg consts) ----------------
__global__ void __launch_bounds__(256) k6_out(const float* __restrict__ w3,
                                              const float* __restrict__ b3,
                                              float* __restrict__ out)
{
    int t = threadIdx.x;
    int warp = t >> 5, lane = t & 31;
    float bias = b3[0];

    float ra[16], rd[16], rw[16];
    #pragma unroll
    for (int p = 0; p < 2; p++) {
        int c0 = p * 256 + lane * 8;
        #pragma unroll
        for (int u = 0; u < 8; u++) {
            ra[p * 8 + u] = g_a2[c0 + u];
            rd[p * 8 + u] = g_d2[c0 + u];
            rw[p * 8 + u] = w3[c0 + u];
        }
    }

    int gw = blockIdx.x * 8 + warp;
    int stride = gridDim.x * 8;
    for (int r = gw; r < B_ROWS; r += stride) {
        const __half* row = g_h2h + (size_t)r * HID;
        float acc = 0.f;
        #pragma unroll
        for (int p = 0; p < 2; p++) {
            int c0 = p * 256 + lane * 8;
            uint4 v = *(const uint4*)(row + c0);
            float2 f0 = __half22float2(*(__half2*)&v.x);
            float2 f1 = __half22float2(*(__half2*)&v.y);
            float2 f2 = __half22float2(*(__half2*)&v.z);
            float2 f3 = __half22float2(*(__half2*)&v.w);
            float hv[8] = {f0.x, f0.y, f1.x, f1.y, f2.x, f2.y, f3.x, f3.y};
            #pragma unroll
            for (int u = 0; u < 8; u++) {
                int q = p * 8 + u;
                acc += htanh(fmaf(ra[q], hv[u], rd[q])) * rw[q];
            }
        }
        #pragma unroll
        for (int off = 16; off; off >>= 1) acc += __shfl_xor_sync(0xffffffffu, acc, off);
        if (lane == 0) out[r] = acc + bias;
    }
}

// ---------------- launch ----------------
extern "C" void kernel_launch(void* const* d_in, const int* in_sizes, int n_in,
                              void* d_out, int out_size)
{
    const float* x     = (const float*)d_in[0];
    const float* tset  = (const float*)d_in[1];
    const float* tenv  = (const float*)d_in[2];
    const float* ctab  = (const float*)d_in[3];
    const float* w1    = (const float*)d_in[4];
    const float* g1    = (const float*)d_in[6];
    const float* beta1 = (const float*)d_in[7];
    const float* w2    = (const float*)d_in[8];
    const float* g2    = (const float*)d_in[10];
    const float* beta2 = (const float*)d_in[11];
    const float* w3    = (const float*)d_in[12];
    const float* b3    = (const float*)d_in[13];
    float* out = (float*)d_out;

    static bool attr_set = false;
    if (!attr_set) {
        cudaFuncSetAttribute(k3b_gemm, cudaFuncAttributeMaxDynamicSharedMemorySize, GEMM_SMEM);
        attr_set = true;
    }

    k1_feat<<<NB1, 256>>>(x, tset, tenv, ctab);
    k2_fin1<<<1, 512>>>(w1, g1, beta1);
    k2b_bsplit<<<HID * HID / 256, 256>>>(w2);
    k3a_layer1<<<B_ROWS / 16, 256>>>();
    dim3 g3(4, B_ROWS / 128);
    k3b_gemm<<<g3, GTHREADS, GEMM_SMEM>>>();
    k5_fin2<<<HID, 256>>>(g2, beta2);
    k6_out<<<4096, 256>>>(w3, b3, out);
}

// round 13
// speedup vs baseline: 1.0846x; 1.0151x over previous
#include <cuda_runtime.h>
#include <cuda_fp16.h>
#include <math.h>
#include <stdint.h>

#define B_ROWS 262144
#define HID 512
#define NB1 512
#define NPART 2048         // GEMM bm count = stats partials

// ---------------- device scratch ----------------
__device__ __half g_A[(size_t)B_ROWS * HID];      // t1 fp16 (256 MB)
__device__ __half g_B[HID * HID];                 // [n][k] = w2[k][n] fp16
__device__ __half g_h2h[(size_t)B_ROWS * HID];    // h2 fp16 (256 MB)
__device__ float  g_feat[B_ROWS * 4];
__device__ double g_p1[NB1 * 14];
__device__ float  g_W1eff[4 * HID];
__device__ float  g_shift1[HID];                  // folded: beta1 - meanX @ W1eff
__device__ float  g_p2s[(size_t)HID * NPART];     // TRANSPOSED: [col][part]
__device__ float  g_p2q[(size_t)HID * NPART];
__device__ float  g_a2[HID];
__device__ float  g_d2[HID];

// ---------------- PTX helpers (sm_80-level, safe at compute_103) ----------------
__device__ __forceinline__ uint32_t smem_u32(const void* p) {
    uint32_t a;
    asm("{ .reg .u64 t; cvta.to.shared.u64 t, %1; cvt.u32.u64 %0, t; }" : "=r"(a) : "l"(p));
    return a;
}
#define CP_ASYNC16(dst, src) \
    asm volatile("cp.async.cg.shared.global [%0], [%1], 16;" :: "r"(dst), "l"(src) : "memory")
#define CP_COMMIT() asm volatile("cp.async.commit_group;" ::: "memory")
#define CP_WAIT(n)  asm volatile("cp.async.wait_group %0;" :: "n"(n) : "memory")
#define LDSM_X4(r0, r1, r2, r3, addr) \
    asm volatile("ldmatrix.sync.aligned.m8n8.x4.shared.b16 {%0,%1,%2,%3}, [%4];" \
        : "=r"(r0), "=r"(r1), "=r"(r2), "=r"(r3) : "r"(addr))
#define MMA16816F16(d, a, b0, b1) \
    asm volatile("mma.sync.aligned.m16n8k16.row.col.f32.f16.f16.f32 " \
        "{%0,%1,%2,%3},{%4,%5,%6,%7},{%8,%9},{%0,%1,%2,%3};" \
        : "+f"((d)[0]), "+f"((d)[1]), "+f"((d)[2]), "+f"((d)[3]) \
        : "r"((a)[0]), "r"((a)[1]), "r"((a)[2]), "r"((a)[3]), "r"(b0), "r"(b1))

__device__ __forceinline__ float htanh(float x) {        // HW tanh (validated vs 1e-3 budget)
    float y;
    asm("tanh.approx.f32 %0, %1;" : "=f"(y) : "f"(x));
    return y;
}

// ---------------- K1: features + (sum, second-moment) partials ----------------
__global__ void __launch_bounds__(256) k1_feat(const float* __restrict__ x,
                                               const float* __restrict__ tset,
                                               const float* __restrict__ tenv,
                                               const float* __restrict__ ctab)
{
    __shared__ float sxs[9], sys[14], stab[9 * 14];
    __shared__ float srow[256][17];               // padded: conflict-free
    __shared__ double swred[8][14];               // per-warp partials
    int tid = threadIdx.x;
    int wid = tid >> 5, lane = tid & 31;
    if (tid < 9)   sxs[tid] = tset[tid];
    if (tid < 14)  sys[tid] = tenv[tid];
    if (tid < 126) stab[tid] = ctab[tid];
    __syncthreads();

    double s0 = 0, s1 = 0, s2 = 0, s3 = 0;
    double m00 = 0, m01 = 0, m02 = 0, m03 = 0, m11 = 0, m12 = 0, m13 = 0,
           m22 = 0, m23 = 0, m33 = 0;

    for (int chunk = 0; chunk < 2; chunk++) {
        int base = blockIdx.x * 512 + chunk * 256;
        const float* gsrc = x + (size_t)base * 15;
        for (int i = tid; i < 256 * 15; i += 256) {
            srow[i / 15][i % 15] = gsrc[i];
        }
        __syncthreads();

        int r = base + tid;
        float amb = srow[tid][1], fl = srow[tid][2], fr = srow[tid][3];
        float incar = srow[tid][8], breq = srow[tid][9], cin = srow[tid][10];

        float yq = fminf(fmaxf(amb, sys[0]), sys[13]);
        int j = 0;
        #pragma unroll
        for (int k = 1; k <= 12; k++) j += (sys[k] <= yq);
        float y0 = sys[j], y1 = sys[j + 1];
        float ty = (yq - y0) / (y1 - y0);

        auto interp = [&](float xq) -> float {
            xq = fminf(fmaxf(xq, sxs[0]), sxs[8]);
            int i = 0;
            #pragma unroll
            for (int k = 1; k <= 7; k++) i += (sxs[k] <= xq);
            float x0 = sxs[i], x1 = sxs[i + 1];
            float tx = (xq - x0) / (x1 - x0);
            float f00 = stab[i * 14 + j],       f01 = stab[i * 14 + j + 1];
            float f10 = stab[(i + 1) * 14 + j], f11 = stab[(i + 1) * 14 + j + 1];
            return f00 * (1.f - tx) * (1.f - ty) + f10 * tx * (1.f - ty)
                 + f01 * (1.f - tx) * ty        + f11 * tx * ty;
        };

        float f0 = interp(fl) - incar;
        float f1 = interp(fr) - incar;
        float f2 = amb;
        float f3 = breq - cin;
        *(float4*)&g_feat[(size_t)r * 4] = make_float4(f0, f1, f2, f3);

        s0 += f0; s1 += f1; s2 += f2; s3 += f3;
        m00 += (double)f0 * f0; m01 += (double)f0 * f1; m02 += (double)f0 * f2; m03 += (double)f0 * f3;
        m11 += (double)f1 * f1; m12 += (double)f1 * f2; m13 += (double)f1 * f3;
        m22 += (double)f2 * f2; m23 += (double)f2 * f3; m33 += (double)f3 * f3;
        __syncthreads();
    }

    // warp-shuffle reduction of the 14 double quantities
    double vals[14] = {s0, s1, s2, s3, m00, m01, m02, m03, m11, m12, m13, m22, m23, m33};
    #pragma unroll
    for (int q = 0; q < 14; q++) {
        double v = vals[q];
        #pragma unroll
        for (int off = 16; off; off >>= 1)
            v += __shfl_xor_sync(0xffffffffu, v, off);
        if (lane == 0) swred[wid][q] = v;
    }
    __syncthreads();
    if (tid < 14) {
        double s = 0;
        #pragma unroll
        for (int w = 0; w < 8; w++) s += swred[w][tid];
        g_p1[blockIdx.x * 14 + tid] = s;
    }
}

// ---------------- K2: finalize layer-1 BN fold (mean folded into shift) ----------------
__global__ void k2_fin1(const float* __restrict__ w1,
                        const float* __restrict__ g1,
                        const float* __restrict__ beta1)
{
    __shared__ double acc[14];
    __shared__ float C[4][4];
    __shared__ float sMean[4];
    int tid = threadIdx.x;
    if (tid < 14) {
        double s = 0;
        for (int p = 0; p < NB1; p++) s += g_p1[p * 14 + tid];
        acc[tid] = s;
    }
    __syncthreads();
    if (tid == 0) {
        double inv = 1.0 / (double)B_ROWS;
        double mm[4];
        for (int a = 0; a < 4; a++) { mm[a] = acc[a] * inv; sMean[a] = (float)mm[a]; }
        double M[4][4];
        int idx = 4;
        for (int a = 0; a < 4; a++)
            for (int b = a; b < 4; b++) M[a][b] = acc[idx++] * inv;
        for (int a = 0; a < 4; a++)
            for (int b = a; b < 4; b++) {
                double c = M[a][b] - mm[a] * mm[b];
                C[a][b] = (float)c; C[b][a] = (float)c;
            }
    }
    __syncthreads();
    if (tid < HID) {
        float w[4];
        for (int a = 0; a < 4; a++) w[a] = w1[a * HID + tid];
        float var = 0.f;
        for (int a = 0; a < 4; a++)
            for (int b = 0; b < 4; b++) var += w[a] * C[a][b] * w[b];
        float s = g1[tid] * rsqrtf(var + 1e-5f);
        float we[4];
        for (int a = 0; a < 4; a++) { we[a] = w[a] * s; g_W1eff[a * HID + tid] = we[a]; }
        g_shift1[tid] = beta1[tid]
                      - (sMean[0] * we[0] + sMean[1] * we[1] + sMean[2] * we[2] + sMean[3] * we[3]);
    }
}

// ---------------- K2b: transpose w2 -> B [n][k] fp16 ----------------
__global__ void k2b_bsplit(const float* __restrict__ w2)
{
    int idx = blockIdx.x * 256 + threadIdx.x;
    int n = idx >> 9, k = idx & 511;
    g_B[n * HID + k] = __float2half_rn(w2[k * HID + n]);
}

// ---------------- K3a: t1 = tanh(feat @ W1eff + shift) -> fp16 (R10 version) ----------------
__global__ void __launch_bounds__(256) k3a_layer1()
{
    int tid = threadIdx.x;
    int jc = (tid & 127) * 4;
    int r0 = blockIdx.x * 16 + (tid >> 7) * 8;

    float4 w0 = *(const float4*)&g_W1eff[0 * HID + jc];
    float4 w1v = *(const float4*)&g_W1eff[1 * HID + jc];
    float4 w2v = *(const float4*)&g_W1eff[2 * HID + jc];
    float4 w3v = *(const float4*)&g_W1eff[3 * HID + jc];
    float4 sh = *(const float4*)&g_shift1[jc];

    #pragma unroll
    for (int rr = 0; rr < 8; rr++) {
        int r = r0 + rr;
        float4 f = *(const float4*)&g_feat[(size_t)r * 4];
        float v0 = f.x * w0.x + f.y * w1v.x + f.z * w2v.x + f.w * w3v.x + sh.x;
        float v1 = f.x * w0.y + f.y * w1v.y + f.z * w2v.y + f.w * w3v.y + sh.y;
        float v2 = f.x * w0.z + f.y * w1v.z + f.z * w2v.z + f.w * w3v.z + sh.z;
        float v3 = f.x * w0.w + f.y * w1v.w + f.z * w2v.w + f.w * w3v.w + sh.w;
        __half2 p0 = __floats2half2_rn(htanh(v0), htanh(v1));
        __half2 p1 = __floats2half2_rn(htanh(v2), htanh(v3));
        uint2 pk = make_uint2(*(uint32_t*)&p0, *(uint32_t*)&p1);
        *(uint2*)(g_A + (size_t)r * HID + jc) = pk;
    }
}

// ---------------- K3b: h2 = t1 @ w2 (fp16 mma.sync) + fused column stats ----------------
// CTA tile 128x128, 4 warps (warp tile 64x64), KSTAGE=64, 3-deep cp.async ring,
// intra-stage register fragment double-buffering.
#define KSTAGE 64
#define ROWPAD 144                     // 128B data + 16B pad (conflict-free ldmatrix)
#define OFF_A 0
#define OFF_B (128 * ROWPAD)           // 18432
#define STAGEB (256 * ROWPAD)          // 36864
#define NSTG 3
#define GEMM_SMEM (NSTG * STAGEB)      // 110592 (2 CTAs/SM = 221 KB)
#define RSTRIDE 136                    // epilogue staging row stride in halves (272B)
#define SST_OFF 36864                  // stats scratch (buffer-1 region, post-loop only)
#define GTHREADS 128

__global__ void __launch_bounds__(GTHREADS, 2) k3b_gemm()
{
    extern __shared__ char smem[];
    const uint32_t sb = smem_u32(smem);
    const int tid = threadIdx.x;
    const int wid = tid >> 5, lane = tid & 31;
    const int bn = blockIdx.x, bm = blockIdx.y;
    const size_t arow0 = (size_t)bm * 128;
    const int ncol0 = bn * 128;

    auto issue_stage = [&](int st) {
        uint32_t stg = sb + (st % NSTG) * STAGEB;
        int kk = st * KSTAGE;
        #pragma unroll
        for (int h = 0; h < 16; h++) {
            int idx = tid + h * GTHREADS;       // 2048 chunks of 16B
            int r = (idx & 1023) >> 3, c = idx & 7;
            uint32_t doff = (uint32_t)r * ROWPAD + c * 16;
            if (idx < 1024) {
                CP_ASYNC16(stg + OFF_A + doff, g_A + (arow0 + r) * HID + kk + c * 8);
            } else {
                CP_ASYNC16(stg + OFF_B + doff, g_B + (size_t)(ncol0 + r) * HID + kk + c * 8);
            }
        }
    };

    issue_stage(0); CP_COMMIT();
    issue_stage(1); CP_COMMIT();

    const int warp_m = wid & 1;        // 2 warp rows of 64
    const int warp_n = wid >> 1;       // 2 warp cols of 64

    float acc[4][8][4];
    #pragma unroll
    for (int i = 0; i < 4; i++)
        #pragma unroll
        for (int j = 0; j < 8; j++)
            #pragma unroll
            for (int q = 0; q < 4; q++) acc[i][j][q] = 0.f;

    const int a_row = warp_m * 64 + (lane & 15);
    const uint32_t a_koff = (lane >> 4) * 16;
    const int b_row = warp_n * 64 + (lane & 7) + ((lane >> 4) & 1) * 8;
    const uint32_t b_koff = ((lane >> 3) & 1) * 16;

    // register fragment double buffers
    uint32_t fa[2][4][4], fb[2][4][4];

#define LOADF(STG, KS, BUF) do {                                                  \
        uint32_t _kb = (uint32_t)(KS) * 32;                                       \
        _Pragma("unroll")                                                         \
        for (int _im = 0; _im < 4; _im++) {                                       \
            uint32_t _aa = (STG) + OFF_A + (uint32_t)(a_row + _im * 16) * ROWPAD + _kb + a_koff; \
            LDSM_X4(fa[BUF][_im][0], fa[BUF][_im][1], fa[BUF][_im][2], fa[BUF][_im][3], _aa);    \
        }                                                                         \
        _Pragma("unroll")                                                         \
        for (int _ng = 0; _ng < 4; _ng++) {                                       \
            uint32_t _bb = (STG) + OFF_B + (uint32_t)(b_row + _ng * 16) * ROWPAD + _kb + b_koff; \
            LDSM_X4(fb[BUF][_ng][0], fb[BUF][_ng][1], fb[BUF][_ng][2], fb[BUF][_ng][3], _bb);    \
        }                                                                         \
    } while (0)

#define MMA_ALL(BUF) do {                                                         \
        _Pragma("unroll")                                                         \
        for (int _ng = 0; _ng < 4; _ng++) {                                       \
            _Pragma("unroll")                                                     \
            for (int _im = 0; _im < 4; _im++) {                                   \
                MMA16816F16(acc[_im][_ng * 2 + 0], fa[BUF][_im], fb[BUF][_ng][0], fb[BUF][_ng][1]); \
                MMA16816F16(acc[_im][_ng * 2 + 1], fa[BUF][_im], fb[BUF][_ng][2], fb[BUF][_ng][3]); \
            }                                                                     \
        }                                                                         \
    } while (0)

    for (int s = 0; s < 8; s++) {
        CP_WAIT(1);
        __syncthreads();

        uint32_t stg = sb + (s % NSTG) * STAGEB;
        LOADF(stg, 0, 0);               // only exposed LDSM latency per stage

        #pragma unroll
        for (int ks = 0; ks < 4; ks++) {
            const int cb = ks & 1;
            if (ks < 3) LOADF(stg, ks + 1, cb ^ 1);   // prefetch next k-step
            if (ks == 0) {
                if (s + 2 < 8) issue_stage(s + 2);
                CP_COMMIT();
            }
            MMA_ALL(cb);
        }
    }
    CP_WAIT(0);
    __syncthreads();

    // ---- epilogue 1: pack fp16 into smem staging (conflict-free) ----
    __half* hst = (__half*)smem;
    #pragma unroll
    for (int im = 0; im < 4; im++) {
        #pragma unroll
        for (int half = 0; half < 2; half++) {
            int row = warp_m * 64 + im * 16 + (lane >> 2) + half * 8;
            int colb = warp_n * 64 + (lane & 3) * 2;
            #pragma unroll
            for (int ng2 = 0; ng2 < 8; ng2++) {
                __half2 hv = __floats2half2_rn(acc[im][ng2][2 * half], acc[im][ng2][2 * half + 1]);
                *(__half2*)&hst[row * RSTRIDE + colb + ng2 * 8] = hv;
            }
        }
    }

    // ---- epilogue 2: fused column sum/sumsq partials ----
    float* sst = (float*)(smem + SST_OFF);
    #pragma unroll
    for (int ng2 = 0; ng2 < 8; ng2++) {
        #pragma unroll
        for (int e = 0; e < 2; e++) {
            float s = 0.f, q = 0.f;
            #pragma unroll
            for (int im = 0; im < 4; im++) {
                #pragma unroll
                for (int half = 0; half < 2; half++) {
                    float v = acc[im][ng2][2 * half + e];
                    s += v; q += v * v;
                }
            }
            #pragma unroll
            for (int off = 4; off < 32; off <<= 1) {
                s += __shfl_xor_sync(0xffffffffu, s, off);
                q += __shfl_xor_sync(0xffffffffu, q, off);
            }
            if (lane < 4) {
                int col = warp_n * 64 + ng2 * 8 + lane * 2 + e;
                sst[(warp_m * 128 + col) * 2 + 0] = s;
                sst[(warp_m * 128 + col) * 2 + 1] = q;
            }
        }
    }
    __syncthreads();

    // ---- epilogue 3: coalesced fp16 stores from staging ----
    #pragma unroll
    for (int it = 0; it < 16; it++) {
        int g = it * GTHREADS + tid;
        int row = g >> 4, ch = g & 15;
        uint4 v = *(uint4*)&hst[row * RSTRIDE + ch * 8];
        *(uint4*)(g_h2h + (arow0 + row) * HID + ncol0 + ch * 8) = v;
    }

    // ---- epilogue 4: reduce stats, write TRANSPOSED partials [col][part] ----
    #pragma unroll
    for (int g = tid; g < 256; g += GTHREADS) {
        int col = g >> 1, sq = g & 1;
        float v = sst[(0 * 128 + col) * 2 + sq] + sst[(1 * 128 + col) * 2 + sq];
        size_t gidx = (size_t)(bn * 128 + col) * NPART + bm;
        if (sq == 0) g_p2s[gidx] = v; else g_p2q[gidx] = v;
    }
#undef LOADF
#undef MMA_ALL
}

// ---------------- K5: finalize layer-2 BN fold (coalesced transposed reads) ----------------
__global__ void k5_fin2(const float* __restrict__ g2, const float* __restrict__ beta2)
{
    int c = blockIdx.x;
    int t = threadIdx.x;
    double s = 0, q = 0;
    for (int p = t; p < NPART; p += 256) {
        s += (double)g_p2s[(size_t)c * NPART + p];
        q += (double)g_p2q[(size_t)c * NPART + p];
    }
    __shared__ double rs[256], rq[256];
    rs[t] = s; rq[t] = q;
    __syncthreads();
    for (int off = 128; off > 0; off >>= 1) {
        if (t < off) { rs[t] += rs[t + off]; rq[t] += rq[t + off]; }
        __syncthreads();
    }
    if (t == 0) {
        double mu  = rs[0] / (double)B_ROWS;
        double var = rq[0] / (double)B_ROWS - mu * mu;
        float a = g2[c] * rsqrtf((float)var + 1e-5f);
        g_a2[c] = a;
        g_d2[c] = beta2[c] - (float)mu * a;
    }
}

// ---------------- K6: out = tanh(a2*h2 + d2) @ w3 + b3 (HW tanh, reg consts) ----------------
__global__ void __launch_bounds__(256) k6_out(const float* __restrict__ w3,
                                              const float* __restrict__ b3,
                                              float* __restrict__ out)
{
    int t = threadIdx.x;
    int warp = t >> 5, lane = t & 31;
    float bias = b3[0];

    float ra[16], rd[16], rw[16];
    #pragma unroll
    for (int p = 0; p < 2; p++) {
        int c0 = p * 256 + lane * 8;
        #pragma unroll
        for (int u = 0; u < 8; u++) {
            ra[p * 8 + u] = g_a2[c0 + u];
            rd[p * 8 + u] = g_d2[c0 + u];
            rw[p * 8 + u] = w3[c0 + u];
        }
    }

    int gw = blockIdx.x * 8 + warp;
    int stride = gridDim.x * 8;
    for (int r = gw; r < B_ROWS; r += stride) {
        const __half* row = g_h2h + (size_t)r * HID;
        float acc = 0.f;
        #pragma unroll
        for (int p = 0; p < 2; p++) {
            int c0 = p * 256 + lane * 8;
            uint4 v = *(const uint4*)(row + c0);
            float2 f0 = __half22float2(*(__half2*)&v.x);
            float2 f1 = __half22float2(*(__half2*)&v.y);
            float2 f2 = __half22float2(*(__half2*)&v.z);
            float2 f3 = __half22float2(*(__half2*)&v.w);
            float hv[8] = {f0.x, f0.y, f1.x, f1.y, f2.x, f2.y, f3.x, f3.y};
            #pragma unroll
            for (int u = 0; u < 8; u++) {
                int q = p * 8 + u;
                acc += htanh(fmaf(ra[q], hv[u], rd[q])) * rw[q];
            }
        }
        #pragma unroll
        for (int off = 16; off; off >>= 1) acc += __shfl_xor_sync(0xffffffffu, acc, off);
        if (lane == 0) out[r] = acc + bias;
    }
}

// ---------------- launch ----------------
extern "C" void kernel_launch(void* const* d_in, const int* in_sizes, int n_in,
                              void* d_out, int out_size)
{
    const float* x     = (const float*)d_in[0];
    const float* tset  = (const float*)d_in[1];
    const float* tenv  = (const float*)d_in[2];
    const float* ctab  = (const float*)d_in[3];
    const float* w1    = (const float*)d_in[4];
    const float* g1    = (const float*)d_in[6];
    const float* beta1 = (const float*)d_in[7];
    const float* w2    = (const float*)d_in[8];
    const float* g2    = (const float*)d_in[10];
    const float* beta2 = (const float*)d_in[11];
    const float* w3    = (const float*)d_in[12];
    const float* b3    = (const float*)d_in[13];
    float* out = (float*)d_out;

    static bool attr_set = false;
    if (!attr_set) {
        cudaFuncSetAttribute(k3b_gemm, cudaFuncAttributeMaxDynamicSharedMemorySize, GEMM_SMEM);
        attr_set = true;
    }

    k1_feat<<<NB1, 256>>>(x, tset, tenv, ctab);
    k2_fin1<<<1, 512>>>(w1, g1, beta1);
    k2b_bsplit<<<HID * HID / 256, 256>>>(w2);
    k3a_layer1<<<B_ROWS / 16, 256>>>();
    dim3 g3(4, B_ROWS / 128);
    k3b_gemm<<<g3, GTHREADS, GEMM_SMEM>>>();
    k5_fin2<<<HID, 256>>>(g2, beta2);
    k6_out<<<4096, 256>>>(w3, b3, out);
}

// round 15
// speedup vs baseline: 1.1177x; 1.0305x over previous
#include <cuda_runtime.h>
#include <cuda_fp16.h>
#include <math.h>
#include <stdint.h>

#define B_ROWS 262144
#define HID 512
#define NB1 512
#define NPART 2048         // GEMM bm count = stats partials

// ---------------- device scratch ----------------
__device__ __half g_A[(size_t)B_ROWS * HID];      // t1 fp16 (256 MB)
__device__ __half g_B[HID * HID];                 // [n][k] = w2[k][n] fp16
__device__ __half g_h2h[(size_t)B_ROWS * HID];    // h2 fp16 (256 MB)
__device__ float  g_feat[B_ROWS * 4];
__device__ double g_p1[NB1 * 14];
__device__ float  g_W1eff[4 * HID];
__device__ float  g_shift1[HID];                  // folded: beta1 - meanX @ W1eff
__device__ float  g_p2s[(size_t)HID * NPART];     // TRANSPOSED: [col][part]
__device__ float  g_p2q[(size_t)HID * NPART];
__device__ float  g_a2[HID];
__device__ float  g_d2[HID];

// ---------------- PTX helpers (sm_80-level, safe at compute_103) ----------------
__device__ __forceinline__ uint32_t smem_u32(const void* p) {
    uint32_t a;
    asm("{ .reg .u64 t; cvta.to.shared.u64 t, %1; cvt.u32.u64 %0, t; }" : "=r"(a) : "l"(p));
    return a;
}
#define CP_ASYNC16(dst, src) \
    asm volatile("cp.async.cg.shared.global [%0], [%1], 16;" :: "r"(dst), "l"(src) : "memory")
#define CP_COMMIT() asm volatile("cp.async.commit_group;" ::: "memory")
#define CP_WAIT(n)  asm volatile("cp.async.wait_group %0;" :: "n"(n) : "memory")
#define LDSM_X4(r0, r1, r2, r3, addr) \
    asm volatile("ldmatrix.sync.aligned.m8n8.x4.shared.b16 {%0,%1,%2,%3}, [%4];" \
        : "=r"(r0), "=r"(r1), "=r"(r2), "=r"(r3) : "r"(addr))
#define MMA16816F16(d, a, b0, b1) \
    asm volatile("mma.sync.aligned.m16n8k16.row.col.f32.f16.f16.f32 " \
        "{%0,%1,%2,%3},{%4,%5,%6,%7},{%8,%9},{%0,%1,%2,%3};" \
        : "+f"((d)[0]), "+f"((d)[1]), "+f"((d)[2]), "+f"((d)[3]) \
        : "r"((a)[0]), "r"((a)[1]), "r"((a)[2]), "r"((a)[3]), "r"(b0), "r"(b1))

__device__ __forceinline__ float htanh(float x) {        // HW tanh (validated vs 1e-3 budget)
    float y;
    asm("tanh.approx.f32 %0, %1;" : "=f"(y) : "f"(x));
    return y;
}

// ---------------- K1: features + (sum, second-moment) partials ----------------
__global__ void __launch_bounds__(256) k1_feat(const float* __restrict__ x,
                                               const float* __restrict__ tset,
                                               const float* __restrict__ tenv,
                                               const float* __restrict__ ctab)
{
    __shared__ float sxs[9], sys[14], stab[9 * 14];
    __shared__ float srow[256][17];               // padded: conflict-free
    __shared__ double swred[8][14];               // per-warp partials
    int tid = threadIdx.x;
    int wid = tid >> 5, lane = tid & 31;
    if (tid < 9)   sxs[tid] = tset[tid];
    if (tid < 14)  sys[tid] = tenv[tid];
    if (tid < 126) stab[tid] = ctab[tid];
    __syncthreads();

    double s0 = 0, s1 = 0, s2 = 0, s3 = 0;
    double m00 = 0, m01 = 0, m02 = 0, m03 = 0, m11 = 0, m12 = 0, m13 = 0,
           m22 = 0, m23 = 0, m33 = 0;

    for (int chunk = 0; chunk < 2; chunk++) {
        int base = blockIdx.x * 512 + chunk * 256;
        const float* gsrc = x + (size_t)base * 15;
        for (int i = tid; i < 256 * 15; i += 256) {
            srow[i / 15][i % 15] = gsrc[i];
        }
        __syncthreads();

        int r = base + tid;
        float amb = srow[tid][1], fl = srow[tid][2], fr = srow[tid][3];
        float incar = srow[tid][8], breq = srow[tid][9], cin = srow[tid][10];

        float yq = fminf(fmaxf(amb, sys[0]), sys[13]);
        int j = 0;
        #pragma unroll
        for (int k = 1; k <= 12; k++) j += (sys[k] <= yq);
        float y0 = sys[j], y1 = sys[j + 1];
        float ty = (yq - y0) / (y1 - y0);

        auto interp = [&](float xq) -> float {
            xq = fminf(fmaxf(xq, sxs[0]), sxs[8]);
            int i = 0;
            #pragma unroll
            for (int k = 1; k <= 7; k++) i += (sxs[k] <= xq);
            float x0 = sxs[i], x1 = sxs[i + 1];
            float tx = (xq - x0) / (x1 - x0);
            float f00 = stab[i * 14 + j],       f01 = stab[i * 14 + j + 1];
            float f10 = stab[(i + 1) * 14 + j], f11 = stab[(i + 1) * 14 + j + 1];
            return f00 * (1.f - tx) * (1.f - ty) + f10 * tx * (1.f - ty)
                 + f01 * (1.f - tx) * ty        + f11 * tx * ty;
        };

        float f0 = interp(fl) - incar;
        float f1 = interp(fr) - incar;
        float f2 = amb;
        float f3 = breq - cin;
        *(float4*)&g_feat[(size_t)r * 4] = make_float4(f0, f1, f2, f3);

        s0 += f0; s1 += f1; s2 += f2; s3 += f3;
        m00 += (double)f0 * f0; m01 += (double)f0 * f1; m02 += (double)f0 * f2; m03 += (double)f0 * f3;
        m11 += (double)f1 * f1; m12 += (double)f1 * f2; m13 += (double)f1 * f3;
        m22 += (double)f2 * f2; m23 += (double)f2 * f3; m33 += (double)f3 * f3;
        __syncthreads();
    }

    double vals[14] = {s0, s1, s2, s3, m00, m01, m02, m03, m11, m12, m13, m22, m23, m33};
    #pragma unroll
    for (int q = 0; q < 14; q++) {
        double v = vals[q];
        #pragma unroll
        for (int off = 16; off; off >>= 1)
            v += __shfl_xor_sync(0xffffffffu, v, off);
        if (lane == 0) swred[wid][q] = v;
    }
    __syncthreads();
    if (tid < 14) {
        double s = 0;
        #pragma unroll
        for (int w = 0; w < 8; w++) s += swred[w][tid];
        g_p1[blockIdx.x * 14 + tid] = s;
    }
}

// ---------------- K2: BN fold (block 0) + w2 transpose (blocks 1..512) ----------------
__global__ void __launch_bounds__(512) k2_fin1(const float* __restrict__ w1,
                                               const float* __restrict__ g1,
                                               const float* __restrict__ beta1,
                                               const float* __restrict__ w2)
{
    int tid = threadIdx.x;
    if (blockIdx.x > 0) {
        // w2 transpose: blocks 1..512, 512 threads each -> 262144 elements
        int idx = (blockIdx.x - 1) * 512 + tid;
        int n = idx >> 9, k = idx & 511;
        g_B[n * HID + k] = __float2half_rn(w2[k * HID + n]);
        return;
    }

    __shared__ double acc[14];
    __shared__ float C[4][4];
    __shared__ float sMean[4];
    if (tid < 14) {
        double s = 0;
        for (int p = 0; p < NB1; p++) s += g_p1[p * 14 + tid];
        acc[tid] = s;
    }
    __syncthreads();
    if (tid == 0) {
        double inv = 1.0 / (double)B_ROWS;
        double mm[4];
        for (int a = 0; a < 4; a++) { mm[a] = acc[a] * inv; sMean[a] = (float)mm[a]; }
        double M[4][4];
        int idx = 4;
        for (int a = 0; a < 4; a++)
            for (int b = a; b < 4; b++) M[a][b] = acc[idx++] * inv;
        for (int a = 0; a < 4; a++)
            for (int b = a; b < 4; b++) {
                double c = M[a][b] - mm[a] * mm[b];
                C[a][b] = (float)c; C[b][a] = (float)c;
            }
    }
    __syncthreads();
    if (tid < HID) {
        float w[4];
        for (int a = 0; a < 4; a++) w[a] = w1[a * HID + tid];
        float var = 0.f;
        for (int a = 0; a < 4; a++)
            for (int b = 0; b < 4; b++) var += w[a] * C[a][b] * w[b];
        float s = g1[tid] * rsqrtf(var + 1e-5f);
        float we[4];
        for (int a = 0; a < 4; a++) { we[a] = w[a] * s; g_W1eff[a * HID + tid] = we[a]; }
        g_shift1[tid] = beta1[tid]
                      - (sMean[0] * we[0] + sMean[1] * we[1] + sMean[2] * we[2] + sMean[3] * we[3]);
    }
}

// ---------------- K3a: t1 = tanh(feat @ W1eff + shift) -> fp16 ----------------
__global__ void __launch_bounds__(256) k3a_layer1()
{
    int tid = threadIdx.x;
    int jc = (tid & 127) * 4;
    int r0 = blockIdx.x * 16 + (tid >> 7) * 8;

    float4 w0 = *(const float4*)&g_W1eff[0 * HID + jc];
    float4 w1v = *(const float4*)&g_W1eff[1 * HID + jc];
    float4 w2v = *(const float4*)&g_W1eff[2 * HID + jc];
    float4 w3v = *(const float4*)&g_W1eff[3 * HID + jc];
    float4 sh = *(const float4*)&g_shift1[jc];

    #pragma unroll
    for (int rr = 0; rr < 8; rr++) {
        int r = r0 + rr;
        float4 f = *(const float4*)&g_feat[(size_t)r * 4];
        float v0 = f.x * w0.x + f.y * w1v.x + f.z * w2v.x + f.w * w3v.x + sh.x;
        float v1 = f.x * w0.y + f.y * w1v.y + f.z * w2v.y + f.w * w3v.y + sh.y;
        float v2 = f.x * w0.z + f.y * w1v.z + f.z * w2v.z + f.w * w3v.z + sh.z;
        float v3 = f.x * w0.w + f.y * w1v.w + f.z * w2v.w + f.w * w3v.w + sh.w;
        __half2 p0 = __floats2half2_rn(htanh(v0), htanh(v1));
        __half2 p1 = __floats2half2_rn(htanh(v2), htanh(v3));
        uint2 pk = make_uint2(*(uint32_t*)&p0, *(uint32_t*)&p1);
        *(uint2*)(g_A + (size_t)r * HID + jc) = pk;
    }
}

// ---------------- K3b: h2 = t1 @ w2 (fp16 mma.sync) + fused column stats ----------------
#define KSTAGE 64
#define ROWPAD 144                     // 128B data + 16B pad (conflict-free ldmatrix)
#define OFF_A 0
#define OFF_B (128 * ROWPAD)           // 18432
#define STAGEB (256 * ROWPAD)          // 36864
#define NSTG 3
#define GEMM_SMEM (NSTG * STAGEB)      // 110592 (2 CTAs/SM = 221 KB)
#define RSTRIDE 136                    // epilogue staging row stride in halves (272B)
#define SST_OFF 36864                  // stats scratch (buffer-1 region, post-loop only)
#define GTHREADS 128

__global__ void __launch_bounds__(GTHREADS, 2) k3b_gemm()
{
    extern __shared__ char smem[];
    const uint32_t sb = smem_u32(smem);
    const int tid = threadIdx.x;
    const int wid = tid >> 5, lane = tid & 31;
    const int bn = blockIdx.x, bm = blockIdx.y;
    const size_t arow0 = (size_t)bm * 128;
    const int ncol0 = bn * 128;

    auto issue_stage = [&](int st) {
        uint32_t stg = sb + (st % NSTG) * STAGEB;
        int kk = st * KSTAGE;
        #pragma unroll
        for (int h = 0; h < 16; h++) {
            int idx = tid + h * GTHREADS;       // 2048 chunks of 16B
            int r = (idx & 1023) >> 3, c = idx & 7;
            uint32_t doff = (uint32_t)r * ROWPAD + c * 16;
            if (idx < 1024) {
                CP_ASYNC16(stg + OFF_A + doff, g_A + (arow0 + r) * HID + kk + c * 8);
            } else {
                CP_ASYNC16(stg + OFF_B + doff, g_B + (size_t)(ncol0 + r) * HID + kk + c * 8);
            }
        }
    };

    issue_stage(0); CP_COMMIT();
    issue_stage(1); CP_COMMIT();

    const int warp_m = wid & 1;        // 2 warp rows of 64
    const int warp_n = wid >> 1;       // 2 warp cols of 64

    float acc[4][8][4];
    #pragma unroll
    for (int i = 0; i < 4; i++)
        #pragma unroll
        for (int j = 0; j < 8; j++)
            #pragma unroll
            for (int q = 0; q < 4; q++) acc[i][j][q] = 0.f;

    const int a_row = warp_m * 64 + (lane & 15);
    const uint32_t a_koff = (lane >> 4) * 16;
    const int b_row = warp_n * 64 + (lane & 7) + ((lane >> 4) & 1) * 8;
    const uint32_t b_koff = ((lane >> 3) & 1) * 16;

    uint32_t fa[2][4][4], fb[2][4][4];

#define LOADF(STG, KS, BUF) do {                                                  \
        uint32_t _kb = (uint32_t)(KS) * 32;                                       \
        _Pragma("unroll")                                                         \
        for (int _im = 0; _im < 4; _im++) {                                       \
            uint32_t _aa = (STG) + OFF_A + (uint32_t)(a_row + _im * 16) * ROWPAD + _kb + a_koff; \
            LDSM_X4(fa[BUF][_im][0], fa[BUF][_im][1], fa[BUF][_im][2], fa[BUF][_im][3], _aa);    \
        }                                                                         \
        _Pragma("unroll")                                                         \
        for (int _ng = 0; _ng < 4; _ng++) {                                       \
            uint32_t _bb = (STG) + OFF_B + (uint32_t)(b_row + _ng * 16) * ROWPAD + _kb + b_koff; \
            LDSM_X4(fb[BUF][_ng][0], fb[BUF][_ng][1], fb[BUF][_ng][2], fb[BUF][_ng][3], _bb);    \
        }                                                                         \
    } while (0)

#define MMA_ALL(BUF) do {                                                         \
        _Pragma("unroll")                                                         \
        for (int _ng = 0; _ng < 4; _ng++) {                                       \
            _Pragma("unroll")                                                     \
            for (int _im = 0; _im < 4; _im++) {                                   \
                MMA16816F16(acc[_im][_ng * 2 + 0], fa[BUF][_im], fb[BUF][_ng][0], fb[BUF][_ng][1]); \
                MMA16816F16(acc[_im][_ng * 2 + 1], fa[BUF][_im], fb[BUF][_ng][2], fb[BUF][_ng][3]); \
            }                                                                     \
        }                                                                         \
    } while (0)

    for (int s = 0; s < 8; s++) {
        CP_WAIT(1);
        __syncthreads();

        uint32_t stg = sb + (s % NSTG) * STAGEB;
        LOADF(stg, 0, 0);

        #pragma unroll
        for (int ks = 0; ks < 4; ks++) {
            const int cb = ks & 1;
            if (ks < 3) LOADF(stg, ks + 1, cb ^ 1);
            if (ks == 0) {
                if (s + 2 < 8) issue_stage(s + 2);
                CP_COMMIT();
            }
            MMA_ALL(cb);
        }
    }
    CP_WAIT(0);
    __syncthreads();

    // ---- epilogue 1: pack fp16 into smem staging (conflict-free) ----
    __half* hst = (__half*)smem;
    #pragma unroll
    for (int im = 0; im < 4; im++) {
        #pragma unroll
        for (int half = 0; half < 2; half++) {
            int row = warp_m * 64 + im * 16 + (lane >> 2) + half * 8;
            int colb = warp_n * 64 + (lane & 3) * 2;
            #pragma unroll
            for (int ng2 = 0; ng2 < 8; ng2++) {
                __half2 hv = __floats2half2_rn(acc[im][ng2][2 * half], acc[im][ng2][2 * half + 1]);
                *(__half2*)&hst[row * RSTRIDE + colb + ng2 * 8] = hv;
            }
        }
    }

    // ---- epilogue 2: fused column sum/sumsq partials ----
    float* sst = (float*)(smem + SST_OFF);
    #pragma unroll
    for (int ng2 = 0; ng2 < 8; ng2++) {
        #pragma unroll
        for (int e = 0; e < 2; e++) {
            float s = 0.f, q = 0.f;
            #pragma unroll
            for (int im = 0; im < 4; im++) {
                #pragma unroll
                for (int half = 0; half < 2; half++) {
                    float v = acc[im][ng2][2 * half + e];
                    s += v; q += v * v;
                }
            }
            #pragma unroll
            for (int off = 4; off < 32; off <<= 1) {
                s += __shfl_xor_sync(0xffffffffu, s, off);
                q += __shfl_xor_sync(0xffffffffu, q, off);
            }
            if (lane < 4) {
                int col = warp_n * 64 + ng2 * 8 + lane * 2 + e;
                sst[(warp_m * 128 + col) * 2 + 0] = s;
                sst[(warp_m * 128 + col) * 2 + 1] = q;
            }
        }
    }
    __syncthreads();

    // ---- epilogue 3: coalesced fp16 stores from staging ----
    #pragma unroll
    for (int it = 0; it < 16; it++) {
        int g = it * GTHREADS + tid;
        int row = g >> 4, ch = g & 15;
        uint4 v = *(uint4*)&hst[row * RSTRIDE + ch * 8];
        *(uint4*)(g_h2h + (arow0 + row) * HID + ncol0 + ch * 8) = v;
    }

    // ---- epilogue 4: reduce stats, write TRANSPOSED partials [col][part] ----
    #pragma unroll
    for (int g = tid; g < 256; g += GTHREADS) {
        int col = g >> 1, sq = g & 1;
        float v = sst[(0 * 128 + col) * 2 + sq] + sst[(1 * 128 + col) * 2 + sq];
        size_t gidx = (size_t)(bn * 128 + col) * NPART + bm;
        if (sq == 0) g_p2s[gidx] = v; else g_p2q[gidx] = v;
    }
#undef LOADF
#undef MMA_ALL
}

// ---------------- K5: finalize layer-2 BN fold (coalesced transposed reads) ----------------
__global__ void k5_fin2(const float* __restrict__ g2, const float* __restrict__ beta2)
{
    int c = blockIdx.x;
    int t = threadIdx.x;
    double s = 0, q = 0;
    for (int p = t; p < NPART; p += 256) {
        s += (double)g_p2s[(size_t)c * NPART + p];
        q += (double)g_p2q[(size_t)c * NPART + p];
    }
    __shared__ double rs[256], rq[256];
    rs[t] = s; rq[t] = q;
    __syncthreads();
    for (int off = 128; off > 0; off >>= 1) {
        if (t < off) { rs[t] += rs[t + off]; rq[t] += rq[t + off]; }
        __syncthreads();
    }
    if (t == 0) {
        double mu  = rs[0] / (double)B_ROWS;
        double var = rq[0] / (double)B_ROWS - mu * mu;
        float a = g2[c] * rsqrtf((float)var + 1e-5f);
        g_a2[c] = a;
        g_d2[c] = beta2[c] - (float)mu * a;
    }
}

// ---------------- K6: out = tanh(a2*h2 + d2) @ w3 + b3 (2-row unroll, HW tanh) ----------------
__global__ void __launch_bounds__(256) k6_out(const float* __restrict__ w3,
                                              const float* __restrict__ b3,
                                              float* __restrict__ out)
{
    int t = threadIdx.x;
    int warp = t >> 5, lane = t & 31;
    float bias = b3[0];

    float ra[16], rd[16], rw[16];
    #pragma unroll
    for (int p = 0; p < 2; p++) {
        int c0 = p * 256 + lane * 8;
        #pragma unroll
        for (int u = 0; u < 8; u++) {
            ra[p * 8 + u] = g_a2[c0 + u];
            rd[p * 8 + u] = g_d2[c0 + u];
            rw[p * 8 + u] = w3[c0 + u];
        }
    }

    const int stride = gridDim.x * 8;          // 32768 warps
    int gw = blockIdx.x * 8 + warp;
    for (int r = gw; r < B_ROWS; r += 2 * stride) {
        int r2 = r + stride;
        const __half* row0 = g_h2h + (size_t)r * HID;
        const __half* row1 = g_h2h + (size_t)r2 * HID;
        // issue all 4 independent 16B loads up front (MLP=4)
        uint4 v00 = *(const uint4*)(row0 + lane * 8);
        uint4 v01 = *(const uint4*)(row0 + 256 + lane * 8);
        uint4 v10 = *(const uint4*)(row1 + lane * 8);
        uint4 v11 = *(const uint4*)(row1 + 256 + lane * 8);

        float acc0 = 0.f, acc1 = 0.f;
        const uint4* vs[4] = {&v00, &v01, &v10, &v11};
        #pragma unroll
        for (int half_sel = 0; half_sel < 4; half_sel++) {
            const uint4& v = *vs[half_sel];
            int p = half_sel & 1;
            float2 f0 = __half22float2(*(__half2*)&v.x);
            float2 f1 = __half22float2(*(__half2*)&v.y);
            float2 f2 = __half22float2(*(__half2*)&v.z);
            float2 f3 = __half22float2(*(__half2*)&v.w);
            float hv[8] = {f0.x, f0.y, f1.x, f1.y, f2.x, f2.y, f3.x, f3.y};
            float a = 0.f;
            #pragma unroll
            for (int u = 0; u < 8; u++) {
                int q = p * 8 + u;
                a += htanh(fmaf(ra[q], hv[u], rd[q])) * rw[q];
            }
            if (half_sel < 2) acc0 += a; else acc1 += a;
        }
        #pragma unroll
        for (int off = 16; off; off >>= 1) {
            acc0 += __shfl_xor_sync(0xffffffffu, acc0, off);
            acc1 += __shfl_xor_sync(0xffffffffu, acc1, off);
        }
        if (lane == 0) { out[r] = acc0 + bias; out[r2] = acc1 + bias; }
    }
}

// ---------------- launch ----------------
extern "C" void kernel_launch(void* const* d_in, const int* in_sizes, int n_in,
                              void* d_out, int out_size)
{
    const float* x     = (const float*)d_in[0];
    const float* tset  = (const float*)d_in[1];
    const float* tenv  = (const float*)d_in[2];
    const float* ctab  = (const float*)d_in[3];
    const float* w1    = (const float*)d_in[4];
    const float* g1    = (const float*)d_in[6];
    const float* beta1 = (const float*)d_in[7];
    const float* w2    = (const float*)d_in[8];
    const float* g2    = (const float*)d_in[10];
    const float* beta2 = (const float*)d_in[11];
    const float* w3    = (const float*)d_in[12];
    const float* b3    = (const float*)d_in[13];
    float* out = (float*)d_out;

    static bool attr_set = false;
    if (!attr_set) {
        cudaFuncSetAttribute(k3b_gemm, cudaFuncAttributeMaxDynamicSharedMemorySize, GEMM_SMEM);
        attr_set = true;
    }

    k1_feat<<<NB1, 256>>>(x, tset, tenv, ctab);
    k2_fin1<<<513, 512>>>(w1, g1, beta1, w2);      // block 0: fold; blocks 1-512: w2 transpose
    k3a_layer1<<<B_ROWS / 16, 256>>>();
    dim3 g3(4, B_ROWS / 128);
    k3b_gemm<<<g3, GTHREADS, GEMM_SMEM>>>();
    k5_fin2<<<HID, 256>>>(g2, beta2);
    k6_out<<<4096, 256>>>(w3, b3, out);
}